// round 16
// baseline (speedup 1.0000x reference)
#include <cuda_runtime.h>
#include <math.h>

#define NMAX 100000
#define EMAX 1600000
#define H 64
#define ED 32
#define NH 4
#define TOPK 10
#define MAXD 96

typedef unsigned long long u64;

// scratch (static device globals -- zero-initialized at module load)
__device__ float g_hW[NMAX * H];        // 25.6 MB
__device__ float g_s1[NMAX * NH];
__device__ float g_s2[NMAX * NH];
__device__ int   g_deg[NMAX];           // all-zero at entry of each kernel_launch
__device__ int   g_kept[NMAX];          // kept count per node (written every launch)
__device__ int   g_start[NMAX];
__device__ int   g_cursor[NMAX];
__device__ int4  g_cpack[EMAX];         // CSR payload {e, score_bits, row|(lr+1)<<20, 0}
__device__ int4  g_kpack[NMAX * TOPK];  // kept list {e, attn_bits, row|(group<<20), 0}
__device__ u64   g_flags[64];           // lookback flags (epoch<<32)|aggregate
__device__ unsigned g_epoch;
__device__ int   g_done;                // count-blocks completion counter
__device__ int   g_done2;               // scan-blocks completion counter

// ---------------------------------------------------------------------------
// Launch 1 (3 roles): [0,nbC) degree count (+epoch bump), [nbC,nbC+nbS1)
// tiled s1/s2 projections, [then +nbS) scan (spins for counts; highest ids).
// ---------------------------------------------------------------------------
__global__ void __launch_bounds__(256)
k_pre(const float* __restrict__ h,
      const float* __restrict__ attn_w,
      const int* __restrict__ col,
      int n, int e_cnt, int nbC, int nbS1, int nbS) {
    __shared__ float s_h[64][65];
    __shared__ float s_aw[2 * H * NH];
    __shared__ int s_wsum[8];
    __shared__ int s_off;
    __shared__ unsigned s_cur;
    int t = threadIdx.x;

    if (blockIdx.x < nbC) {
        // -------- count role --------
        if (blockIdx.x == 0 && t == 0) atomicAdd(&g_epoch, 1u);
        int i = blockIdx.x * 256 + t;
        if (i < e_cnt) atomicAdd(&g_deg[col[i]], 1);
        __threadfence();
        __syncthreads();
        if (t == 0) atomicAdd(&g_done, 1);
        return;
    }

    if (blockIdx.x < nbC + nbS1) {
        // -------- s1/s2 role: tile of 64 nodes --------
        int base = (blockIdx.x - nbC) * 64;
        {
            const float2* src = reinterpret_cast<const float2*>(attn_w);
            float2* dst = reinterpret_cast<float2*>(s_aw);
            dst[t] = src[t];   // 512 floats
        }
        #pragma unroll
        for (int j = 0; j < 4; j++) {
            int idx = t + j * 256;
            int r = idx >> 4;
            int c = (idx & 15) << 2;
            float4 v = make_float4(0.f, 0.f, 0.f, 0.f);
            if (base + r < n)
                v = reinterpret_cast<const float4*>(h + (size_t)(base + r) * H + c)[0];
            s_h[r][c]     = v.x;
            s_h[r][c + 1] = v.y;
            s_h[r][c + 2] = v.z;
            s_h[r][c + 3] = v.w;
        }
        __syncthreads();
        // 512 dots: thread handles d and d+256
        for (int d = t; d < 512; d += 256) {
            int nl = d >> 3;
            int sub = d & 7;
            int which = sub >> 2, head = sub & 3;
            const float* aw = s_aw + which * H * NH + head;
            float s = 0.f;
            #pragma unroll
            for (int k = 0; k < H; k++) s += s_h[nl][k] * aw[k * NH];
            int node = base + nl;
            if (node < n) {
                if (which == 0) g_s1[node * NH + head] = s;
                else            g_s2[node * NH + head] = s;
            }
        }
        return;
    }

    // -------- scan role --------
    {
        int b = blockIdx.x - nbC - nbS1;
        if (t == 0) {
            while (*(volatile int*)&g_done != nbC) {}
            s_off = 0;
            s_cur = *(volatile unsigned*)&g_epoch;
        }
        __syncthreads();
        __threadfence();
        unsigned cur = s_cur;

        int base = b * 2048 + t * 8;
        int v[8];
        #pragma unroll
        for (int j = 0; j < 8; j++) v[j] = (base + j < n) ? g_deg[base + j] : 0;
        int tsum = 0;
        #pragma unroll
        for (int j = 0; j < 8; j++) { int x = v[j]; v[j] = tsum; tsum += x; }
        int lane = t & 31, wid = t >> 5;
        int x = tsum;
        #pragma unroll
        for (int off = 1; off < 32; off <<= 1) {
            int y = __shfl_up_sync(0xffffffffu, x, off);
            if (lane >= off) x += y;
        }
        if (lane == 31) s_wsum[wid] = x;
        __syncthreads();
        if (t == 0) {
            int a = 0;
            #pragma unroll
            for (int w = 0; w < 8; w++) { int tt = s_wsum[w]; s_wsum[w] = a; a += tt; }
            atomicExch(&g_flags[b], ((u64)cur << 32) | (unsigned)a);
        }
        __syncthreads();
        if (t < b) {
            u64 f;
            do { f = atomicOr(&g_flags[t], 0ULL); } while ((unsigned)(f >> 32) != cur);
            atomicAdd(&s_off, (int)(unsigned)f);
        }
        __syncthreads();
        int excl = s_off + s_wsum[wid] + (x - tsum);
        #pragma unroll
        for (int j = 0; j < 8; j++)
            if (base + j < n) {
                int s = excl + v[j];
                g_start[base + j]  = s;
                g_cursor[base + j] = s;
            }
        __threadfence();
        __syncthreads();
        if (t == 0) {
            int vv = atomicAdd(&g_done2, 1);
            if (vv == nbS - 1) {
                *(volatile int*)&g_done  = 0;
                *(volatile int*)&g_done2 = 0;
            }
        }
    }
}

// ---------------------------------------------------------------------------
// Launch 2 (2 INDEPENDENT roles): [0,nbE) score+scatter (DRAM-bound),
// [nbE,nbE+nbG) lean hW GEMM (FMA-bound) — complementary pipes overlap.
// ---------------------------------------------------------------------------
__global__ void __launch_bounds__(256)
k_mid(const float* __restrict__ h,
      const float* __restrict__ whW,
      const float* __restrict__ whb,
      const float* __restrict__ edge_attr,
      const float* __restrict__ attn_w,
      const int* __restrict__ labels,
      const int* __restrict__ row,
      const int* __restrict__ col,
      int n, int e_cnt, int nbE) {
    __shared__ float s_h[64][65];
    __shared__ float s_w[64 * 64];
    __shared__ float s_b[64];
    __shared__ float s_a3[ED * NH];
    int t = threadIdx.x;

    if (blockIdx.x < nbE) {
        // -------- scatter role (atomic hoisted) --------
        for (int i = t; i < ED * NH; i += blockDim.x)
            s_a3[i] = attn_w[2 * H * NH + i];
        __syncthreads();

        int e = blockIdx.x * 256 + t;
        if (e >= e_cnt) return;
        int r = row[e], c = col[e];
        int p = atomicAdd(&g_cursor[c], 1);
        int lr = labels[r];
        float4 p1 = reinterpret_cast<const float4*>(g_s1)[r];
        float4 p2 = reinterpret_cast<const float4*>(g_s2)[c];
        const float4* ea4 = reinterpret_cast<const float4*>(edge_attr + (size_t)e * ED);
        float4 v0 = ea4[0], v1 = ea4[1], v2 = ea4[2], v3 = ea4[3];
        float4 v4 = ea4[4], v5 = ea4[5], v6 = ea4[6], v7 = ea4[7];
        const float4 vv[8] = {v0, v1, v2, v3, v4, v5, v6, v7};
        float s3[NH] = {0.f, 0.f, 0.f, 0.f};
        #pragma unroll
        for (int q = 0; q < 8; q++) {
            float4 v = vv[q];
            int k = q * 4;
            #pragma unroll
            for (int hd = 0; hd < NH; hd++) {
                s3[hd] += v.x * s_a3[(k    ) * NH + hd];
                s3[hd] += v.y * s_a3[(k + 1) * NH + hd];
                s3[hd] += v.z * s_a3[(k + 2) * NH + hd];
                s3[hd] += v.w * s_a3[(k + 3) * NH + hd];
            }
        }
        float t0 = p1.x + p2.x + s3[0];
        float t1 = p1.y + p2.y + s3[1];
        float t2 = p1.z + p2.z + s3[2];
        float t3 = p1.w + p2.w + s3[3];
        t0 = (t0 >= 0.f) ? t0 : 0.2f * t0;
        t1 = (t1 >= 0.f) ? t1 : 0.2f * t1;
        t2 = (t2 >= 0.f) ? t2 : 0.2f * t2;
        t3 = (t3 >= 0.f) ? t3 : 0.2f * t3;
        float score = 0.25f * (t0 + t1 + t2 + t3);
        g_cpack[p] = make_int4(e, __float_as_int(score), r | ((lr + 1) << 20), 0);
        return;
    }

    // -------- lean hW GEMM role (validated 44-reg shape) --------
    int base = (blockIdx.x - nbE) * 64;
    {
        const float4* src = reinterpret_cast<const float4*>(whW);
        float4* dst = reinterpret_cast<float4*>(s_w);
        #pragma unroll
        for (int j = 0; j < 4; j++) dst[t + j * 256] = src[t + j * 256];
    }
    if (t < 64) s_b[t] = whb[t];
    {
        #pragma unroll
        for (int j = 0; j < 4; j++) {
            int idx = t + j * 256;
            int r = idx >> 4;
            int c = (idx & 15) << 2;
            float4 v = make_float4(0.f, 0.f, 0.f, 0.f);
            if (base + r < n)
                v = reinterpret_cast<const float4*>(h + (size_t)(base + r) * H + c)[0];
            s_h[r][c]     = v.x;
            s_h[r][c + 1] = v.y;
            s_h[r][c + 2] = v.z;
            s_h[r][c + 3] = v.w;
        }
    }
    __syncthreads();

    int nq = t >> 4;
    int cq = t & 15;
    float acc[4][4];
    #pragma unroll
    for (int i = 0; i < 4; i++)
        #pragma unroll
        for (int j = 0; j < 4; j++) acc[i][j] = 0.f;

    #pragma unroll 8
    for (int k = 0; k < 64; k++) {
        float4 b = *reinterpret_cast<const float4*>(&s_w[k * 64 + cq * 4]);
        float a0 = s_h[nq * 4 + 0][k];
        float a1 = s_h[nq * 4 + 1][k];
        float a2 = s_h[nq * 4 + 2][k];
        float a3 = s_h[nq * 4 + 3][k];
        acc[0][0] += a0 * b.x; acc[0][1] += a0 * b.y; acc[0][2] += a0 * b.z; acc[0][3] += a0 * b.w;
        acc[1][0] += a1 * b.x; acc[1][1] += a1 * b.y; acc[1][2] += a1 * b.z; acc[1][3] += a1 * b.w;
        acc[2][0] += a2 * b.x; acc[2][1] += a2 * b.y; acc[2][2] += a2 * b.z; acc[2][3] += a2 * b.w;
        acc[3][0] += a3 * b.x; acc[3][1] += a3 * b.y; acc[3][2] += a3 * b.z; acc[3][3] += a3 * b.w;
    }

    float4 bias = *reinterpret_cast<const float4*>(&s_b[cq * 4]);
    #pragma unroll
    for (int i = 0; i < 4; i++) {
        int node = base + nq * 4 + i;
        if (node < n) {
            float4 v = make_float4(acc[i][0] + bias.x, acc[i][1] + bias.y,
                                   acc[i][2] + bias.z, acc[i][3] + bias.w);
            reinterpret_cast<float4*>(g_hW + (size_t)node * H + cq * 4)[0] = v;
        }
    }
}

// ---------------------------------------------------------------------------
// Launch 3: selection — softmax + top-k rank -> g_kpack, g_kept.
// Zeroes g_deg (last reader) for next replay.
// ---------------------------------------------------------------------------
__global__ void __launch_bounds__(256)
k_select(const int* __restrict__ labels, int n) {
    __shared__ float s_sc[8][MAXD];
    __shared__ int   s_eid[8][MAXD];
    int tid = threadIdx.x;
    int lane = tid & 31, wl = tid >> 5;
    int warpG = (blockIdx.x * blockDim.x + tid) >> 5;
    int nwarps = (gridDim.x * blockDim.x) >> 5;

    for (int node = warpG; node < n; node += nwarps) {
        int d = g_deg[node], st = g_start[node];
        int kk = 0;
        if (d > 0 && d <= 32) {
            int lc = labels[node];
            bool valid = lane < d;
            int4 P = g_cpack[st + (valid ? lane : 0)];
            int e = P.x; float sc = __int_as_float(P.y); int rl = P.z;
            if (!valid) { e = 0x7FFFFFFF; sc = -1e30f; }
            float mx = sc;
            #pragma unroll
            for (int off = 16; off; off >>= 1)
                mx = fmaxf(mx, __shfl_xor_sync(0xffffffffu, mx, off));
            float ex = valid ? expf(sc - mx) : 0.f;
            float sum = ex;
            #pragma unroll
            for (int off = 16; off; off >>= 1)
                sum += __shfl_xor_sync(0xffffffffu, sum, off);
            float invden = 1.f / sum;
            int cnt = 0;
            if (d > TOPK) {
                for (int j = 0; j < d; j++) {
                    float scj = __shfl_sync(0xffffffffu, sc, j);
                    int   ej  = __shfl_sync(0xffffffffu, e,  j);
                    cnt += (scj > sc) || (scj == sc && ej < e);
                }
            }
            bool keep = valid && (cnt < TOPK);
            unsigned bal = __ballot_sync(0xffffffffu, keep);
            kk = __popc(bal);
            int pos = __popc(bal & ((1u << lane) - 1u));
            if (keep) {
                int lr = (rl >> 20) - 1;
                int g = (lr < 0 || lc < 0) ? 2 : ((lr == lc) ? 0 : 1);
                g_kpack[node * TOPK + pos] =
                    make_int4(e, __float_as_int(ex * invden), (rl & 0xFFFFF) | (g << 20), 0);
            }
        } else if (d > 32 && d <= MAXD) {
            int lc = labels[node];
            for (int i = lane; i < d; i += 32) {
                int4 P = g_cpack[st + i];
                s_eid[wl][i] = P.x;
                s_sc[wl][i]  = __int_as_float(P.y);
            }
            __syncwarp();
            float mx = -1e30f;
            for (int i = lane; i < d; i += 32) mx = fmaxf(mx, s_sc[wl][i]);
            #pragma unroll
            for (int off = 16; off; off >>= 1)
                mx = fmaxf(mx, __shfl_xor_sync(0xffffffffu, mx, off));
            float sum = 0.f;
            for (int i = lane; i < d; i += 32) sum += expf(s_sc[wl][i] - mx);
            #pragma unroll
            for (int off = 16; off; off >>= 1)
                sum += __shfl_xor_sync(0xffffffffu, sum, off);
            float invden = 1.f / sum;
            for (int base = 0; base < d; base += 32) {
                int i = base + lane;
                bool valid = (i < d);
                bool keep = false;
                float a = 0.f;
                if (valid) {
                    float sci = s_sc[wl][i];
                    int ei = s_eid[wl][i];
                    int c = 0;
                    for (int j = 0; j < d; j++) {
                        float scj = s_sc[wl][j];
                        c += (scj > sci) || (scj == sci && s_eid[wl][j] < ei);
                    }
                    keep = (c < TOPK);
                    if (keep) a = expf(sci - mx) * invden;
                }
                unsigned bal = __ballot_sync(0xffffffffu, valid && keep);
                int pos = kk + __popc(bal & ((1u << lane) - 1u));
                if (valid && keep) {
                    int rl = g_cpack[st + i].z;
                    int lr = (rl >> 20) - 1;
                    int g = (lr < 0 || lc < 0) ? 2 : ((lr == lc) ? 0 : 1);
                    g_kpack[node * TOPK + pos] =
                        make_int4(s_eid[wl][i], __float_as_int(a), (rl & 0xFFFFF) | (g << 20), 0);
                }
                kk += __popc(bal);
            }
            __syncwarp();
        } else if (d > MAXD) {
            int lc = labels[node];
            float mx = -1e30f;
            for (int i = lane; i < d; i += 32)
                mx = fmaxf(mx, __int_as_float(g_cpack[st + i].y));
            #pragma unroll
            for (int off = 16; off; off >>= 1)
                mx = fmaxf(mx, __shfl_xor_sync(0xffffffffu, mx, off));
            float sum = 0.f;
            for (int i = lane; i < d; i += 32)
                sum += expf(__int_as_float(g_cpack[st + i].y) - mx);
            #pragma unroll
            for (int off = 16; off; off >>= 1)
                sum += __shfl_xor_sync(0xffffffffu, sum, off);
            float invden = 1.f / sum;
            for (int i = 0; i < d; i++) {
                int4 P = g_cpack[st + i];
                float sci = __int_as_float(P.y);
                int c = 0;
                for (int j = lane; j < d; j += 32) {
                    int4 Q = g_cpack[st + j];
                    float scj = __int_as_float(Q.y);
                    c += (scj > sci) || (scj == sci && Q.x < P.x);
                }
                #pragma unroll
                for (int off = 16; off; off >>= 1)
                    c += __shfl_xor_sync(0xffffffffu, c, off);
                if (c < TOPK) {
                    if (lane == 0) {
                        float a = expf(sci - mx) * invden;
                        int rl = P.z;
                        int lr = (rl >> 20) - 1;
                        int g = (lr < 0 || lc < 0) ? 2 : ((lr == lc) ? 0 : 1);
                        g_kpack[node * TOPK + kk] =
                            make_int4(P.x, __float_as_int(a), (rl & 0xFFFFF) | (g << 20), 0);
                    }
                    kk++;
                }
            }
        }
        g_kept[node] = kk;
        g_deg[node]  = 0;     // self-clean for next replay
    }
}

// ---------------------------------------------------------------------------
// Launch 4 (PROFILED): MAC — exact R12 shape + streaming (__stcs) output
// stores so the 76MB write-once out stream doesn't evict L2-resident hW.
// ---------------------------------------------------------------------------
__global__ void __launch_bounds__(256, 2)
k_mac(const float* __restrict__ edge_attr,
      const float* __restrict__ weW,
      const float* __restrict__ web,
      float* __restrict__ out,
      int n) {
    __shared__ float  s_eav[8][TOPK][ED];   // 10 KB: warp-private edge_attr rows
    __shared__ float2 s_hv[8][TOPK][32];    // 20 KB: warp-private hW (2l,2l+1) pairs

    int tid = threadIdx.x;
    int lane = tid & 31, wl = tid >> 5;
    int warpG = (blockIdx.x * blockDim.x + tid) >> 5;
    int nwarps = (gridDim.x * blockDim.x) >> 5;

    // weights for output columns 2*lane, 2*lane+1
    float2 w2[ED];
    #pragma unroll
    for (int k = 0; k < ED; k++)
        w2[k] = reinterpret_cast<const float2*>(weW + k * H)[lane];
    float2 b2 = reinterpret_cast<const float2*>(web)[lane];

    for (int node = warpG; node < n; node += nwarps) {
        int kk = g_kept[node];
        float acc0 = 0.f, acc1 = 0.f, acc2 = 0.f, acc3 = 0.f, acc4 = 0.f, acc5 = 0.f;
        if (kk > 0) {
            int4 P = g_kpack[node * TOPK + (lane < kk ? lane : 0)];
            int   e_reg = P.x;
            float a_reg = __int_as_float(P.y);
            int   meta  = P.z;
            int   r_reg = meta & 0xFFFFF;
            // prefetch: independent coalesced loads, high MLP
            for (int i = 0; i < kk; i++) {
                int e_i = __shfl_sync(0xffffffffu, e_reg, i);
                int r_i = __shfl_sync(0xffffffffu, r_reg, i);
                s_eav[wl][i][lane] = edge_attr[(size_t)e_i * ED + lane];
                s_hv[wl][i][lane]  = reinterpret_cast<const float2*>(g_hW + (size_t)r_i * H)[lane];
            }
            __syncwarp();
            // MAC: float4 broadcast LDS + FFMA (2 cols/lane)
            for (int i = 0; i < kk; i++) {
                float a = __shfl_sync(0xffffffffu, a_reg, i);
                int   g = __shfl_sync(0xffffffffu, meta, i) >> 20;
                float m0 = b2.x, m1 = b2.y;
                const float4* ev = reinterpret_cast<const float4*>(s_eav[wl][i]);
                #pragma unroll
                for (int k4 = 0; k4 < 8; k4++) {
                    float4 v = ev[k4];
                    int k = k4 * 4;
                    m0 += v.x * w2[k].x;     m1 += v.x * w2[k].y;
                    m0 += v.y * w2[k + 1].x; m1 += v.y * w2[k + 1].y;
                    m0 += v.z * w2[k + 2].x; m1 += v.z * w2[k + 2].y;
                    m0 += v.w * w2[k + 3].x; m1 += v.w * w2[k + 3].y;
                }
                float2 hv = s_hv[wl][i][lane];
                m0 = fmaxf(m0 + hv.x, 0.f);
                m1 = fmaxf(m1 + hv.y, 0.f);
                if (g == 0)      { acc0 += a * m0; acc1 += a * m1; }
                else if (g == 1) { acc2 += a * m0; acc3 += a * m1; }
                else             { acc4 += a * m0; acc5 += a * m1; }
            }
            __syncwarp();
        }
        size_t ob = (size_t)node * (3 * H);
        __stcs(reinterpret_cast<float2*>(out + ob) + lane,         make_float2(acc0, acc1));
        __stcs(reinterpret_cast<float2*>(out + ob + H) + lane,     make_float2(acc2, acc3));
        __stcs(reinterpret_cast<float2*>(out + ob + 2 * H) + lane, make_float2(acc4, acc5));
    }
}

// ---------------------------------------------------------------------------
extern "C" void kernel_launch(void* const* d_in, const int* in_sizes, int n_in,
                              void* d_out, int out_size) {
    const float* h         = (const float*)d_in[0];
    const int*   edge_idx  = (const int*)  d_in[1];
    const float* edge_attr = (const float*)d_in[2];
    const int*   labels    = (const int*)  d_in[3];
    const float* attn_w    = (const float*)d_in[4];
    const float* whW       = (const float*)d_in[5];
    const float* whb       = (const float*)d_in[6];
    const float* weW       = (const float*)d_in[7];
    const float* web       = (const float*)d_in[8];
    float* out = (float*)d_out;

    int n = in_sizes[0] / H;
    int e = in_sizes[1] / 2;
    const int* row = edge_idx;
    const int* col = edge_idx + e;

    int nbC  = (e + 255) / 256;
    int nbS1 = (n + 63) / 64;
    int nbS  = (n + 2047) / 2048;   // <= 64
    int nbE  = (e + 255) / 256;
    int nbG  = (n + 63) / 64;

    k_pre<<<nbC + nbS1 + nbS, 256>>>(h, attn_w, col, n, e, nbC, nbS1, nbS);
    k_mid<<<nbE + nbG, 256>>>(h, whW, whb, edge_attr, attn_w, labels, row, col, n, e, nbE);
    k_select<<<592, 256>>>(labels, n);
    k_mac<<<592, 256>>>(edge_attr, weW, web, out, n);   // profiled slot 4
}

// round 17
// speedup vs baseline: 1.0929x; 1.0929x over previous
#include <cuda_runtime.h>
#include <math.h>

#define NMAX 100000
#define EMAX 1600000
#define H 64
#define ED 32
#define NH 4
#define TOPK 10
#define MAXD 96

typedef unsigned long long u64;

// scratch (static device globals -- zero-initialized at module load)
__device__ float g_hW[NMAX * H];        // 25.6 MB
__device__ float g_s1[NMAX * NH];
__device__ float g_s2[NMAX * NH];
__device__ int   g_deg[NMAX];           // all-zero at entry of each kernel_launch
__device__ int   g_start[NMAX];
__device__ int   g_cursor[NMAX];
__device__ int4  g_cpack[EMAX];         // CSR payload {e, score_bits, row|(lr+1)<<20, 0}
__device__ u64   g_flags[64];           // lookback flags (epoch<<32)|aggregate
__device__ unsigned g_epoch;

// ---------------------------------------------------------------------------
// Launch 1 (fused): hW GEMM + s1/s2 (blocks < nbG), degree count + epoch bump.
// ---------------------------------------------------------------------------
__global__ void __launch_bounds__(256)
k_gemm_count(const float* __restrict__ h,
             const float* __restrict__ whW,
             const float* __restrict__ whb,
             const float* __restrict__ attn_w,
             const int* __restrict__ col,
             int n, int e_cnt, int nbG) {
    __shared__ float s_h[64][65];
    __shared__ float s_w[64 * 64];
    __shared__ float s_b[64];
    __shared__ float s_aw[2 * H * NH];
    int t = threadIdx.x;

    if (blockIdx.x >= nbG) {
        if (blockIdx.x == nbG && t == 0) atomicAdd(&g_epoch, 1u);
        int i = (blockIdx.x - nbG) * 256 + t;
        if (i < e_cnt) atomicAdd(&g_deg[col[i]], 1);
        return;
    }

    int base = blockIdx.x * 64;
    {
        const float4* src = reinterpret_cast<const float4*>(whW);
        float4* dst = reinterpret_cast<float4*>(s_w);
        #pragma unroll
        for (int j = 0; j < 4; j++) dst[t + j * 256] = src[t + j * 256];
    }
    if (t < 64) s_b[t] = whb[t];
    {
        const float2* src = reinterpret_cast<const float2*>(attn_w);
        float2* dst = reinterpret_cast<float2*>(s_aw);
        dst[t] = src[t];
    }
    {
        #pragma unroll
        for (int j = 0; j < 4; j++) {
            int idx = t + j * 256;
            int r = idx >> 4;
            int c = (idx & 15) << 2;
            float4 v = make_float4(0.f, 0.f, 0.f, 0.f);
            if (base + r < n)
                v = reinterpret_cast<const float4*>(h + (size_t)(base + r) * H + c)[0];
            s_h[r][c]     = v.x;
            s_h[r][c + 1] = v.y;
            s_h[r][c + 2] = v.z;
            s_h[r][c + 3] = v.w;
        }
    }
    __syncthreads();

    int nq = t >> 4;
    int cq = t & 15;
    float acc[4][4];
    #pragma unroll
    for (int i = 0; i < 4; i++)
        #pragma unroll
        for (int j = 0; j < 4; j++) acc[i][j] = 0.f;

    #pragma unroll 8
    for (int k = 0; k < 64; k++) {
        float4 b = *reinterpret_cast<const float4*>(&s_w[k * 64 + cq * 4]);
        float a0 = s_h[nq * 4 + 0][k];
        float a1 = s_h[nq * 4 + 1][k];
        float a2 = s_h[nq * 4 + 2][k];
        float a3 = s_h[nq * 4 + 3][k];
        acc[0][0] += a0 * b.x; acc[0][1] += a0 * b.y; acc[0][2] += a0 * b.z; acc[0][3] += a0 * b.w;
        acc[1][0] += a1 * b.x; acc[1][1] += a1 * b.y; acc[1][2] += a1 * b.z; acc[1][3] += a1 * b.w;
        acc[2][0] += a2 * b.x; acc[2][1] += a2 * b.y; acc[2][2] += a2 * b.z; acc[2][3] += a2 * b.w;
        acc[3][0] += a3 * b.x; acc[3][1] += a3 * b.y; acc[3][2] += a3 * b.z; acc[3][3] += a3 * b.w;
    }

    float4 bias = *reinterpret_cast<const float4*>(&s_b[cq * 4]);
    #pragma unroll
    for (int i = 0; i < 4; i++) {
        int node = base + nq * 4 + i;
        if (node < n) {
            float4 v = make_float4(acc[i][0] + bias.x, acc[i][1] + bias.y,
                                   acc[i][2] + bias.z, acc[i][3] + bias.w);
            reinterpret_cast<float4*>(g_hW + (size_t)node * H + cq * 4)[0] = v;
        }
    }

    {
        int nl = t >> 3;
        int sub = t & 7;
        int which = sub >> 2, head = sub & 3;
        const float* aw = s_aw + which * H * NH + head;
        #pragma unroll
        for (int pass = 0; pass < 2; pass++) {
            int r = nl + pass * 32;
            int node = base + r;
            float s = 0.f;
            #pragma unroll
            for (int k = 0; k < H; k++) s += s_h[r][k] * aw[k * NH];
            if (node < n) {
                if (which == 0) g_s1[node * NH + head] = s;
                else            g_s2[node * NH + head] = s;
            }
        }
    }
}

// ---------------------------------------------------------------------------
// Launch 2: single-pass scan, epoch-tagged decoupled lookback.
// ---------------------------------------------------------------------------
__global__ void __launch_bounds__(256)
k_scan_onepass(int n) {
    __shared__ int s_wsum[8];
    __shared__ int s_off;
    __shared__ unsigned s_cur;
    int b = blockIdx.x, t = threadIdx.x;
    if (t == 0) { s_off = 0; s_cur = *(volatile unsigned*)&g_epoch; }
    __syncthreads();
    unsigned cur = s_cur;

    int base = b * 2048 + t * 8;
    int v[8];
    #pragma unroll
    for (int j = 0; j < 8; j++) v[j] = (base + j < n) ? g_deg[base + j] : 0;
    int tsum = 0;
    #pragma unroll
    for (int j = 0; j < 8; j++) { int x = v[j]; v[j] = tsum; tsum += x; }
    int lane = t & 31, wid = t >> 5;
    int x = tsum;
    #pragma unroll
    for (int off = 1; off < 32; off <<= 1) {
        int y = __shfl_up_sync(0xffffffffu, x, off);
        if (lane >= off) x += y;
    }
    if (lane == 31) s_wsum[wid] = x;
    __syncthreads();
    if (t == 0) {
        int a = 0;
        #pragma unroll
        for (int w = 0; w < 8; w++) { int tt = s_wsum[w]; s_wsum[w] = a; a += tt; }
        atomicExch(&g_flags[b], ((u64)cur << 32) | (unsigned)a);
    }
    __syncthreads();
    if (t < b) {
        u64 f;
        do { f = atomicOr(&g_flags[t], 0ULL); } while ((unsigned)(f >> 32) != cur);
        atomicAdd(&s_off, (int)(unsigned)f);
    }
    __syncthreads();
    int excl = s_off + s_wsum[wid] + (x - tsum);
    #pragma unroll
    for (int j = 0; j < 8; j++)
        if (base + j < n) {
            int s = excl + v[j];
            g_start[base + j]  = s;
            g_cursor[base + j] = s;
        }
}

// ---------------------------------------------------------------------------
// Launch 3: per-edge score + CSR scatter (hoisted atomic, single int4 store).
// ---------------------------------------------------------------------------
__global__ void __launch_bounds__(256)
k_score_scatter(const int* __restrict__ row,
                const int* __restrict__ col,
                const float* __restrict__ edge_attr,
                const float* __restrict__ attn_w,
                const int* __restrict__ labels,
                int e_cnt) {
    __shared__ float s_a3[ED * NH];
    int tid = threadIdx.x;
    for (int i = tid; i < ED * NH; i += blockDim.x)
        s_a3[i] = attn_w[2 * H * NH + i];
    __syncthreads();

    int e = blockIdx.x * blockDim.x + tid;
    if (e >= e_cnt) return;
    int r = row[e], c = col[e];
    int p = atomicAdd(&g_cursor[c], 1);        // hoisted: overlaps the MAC below
    int lr = labels[r];
    float4 p1 = reinterpret_cast<const float4*>(g_s1)[r];
    float4 p2 = reinterpret_cast<const float4*>(g_s2)[c];
    const float4* ea4 = reinterpret_cast<const float4*>(edge_attr + (size_t)e * ED);
    float4 v0 = ea4[0], v1 = ea4[1], v2 = ea4[2], v3 = ea4[3];
    float4 v4 = ea4[4], v5 = ea4[5], v6 = ea4[6], v7 = ea4[7];
    const float4 vv[8] = {v0, v1, v2, v3, v4, v5, v6, v7};
    float s3[NH] = {0.f, 0.f, 0.f, 0.f};
    #pragma unroll
    for (int q = 0; q < 8; q++) {
        float4 v = vv[q];
        int k = q * 4;
        #pragma unroll
        for (int hd = 0; hd < NH; hd++) {
            s3[hd] += v.x * s_a3[(k    ) * NH + hd];
            s3[hd] += v.y * s_a3[(k + 1) * NH + hd];
            s3[hd] += v.z * s_a3[(k + 2) * NH + hd];
            s3[hd] += v.w * s_a3[(k + 3) * NH + hd];
        }
    }
    float t0 = p1.x + p2.x + s3[0];
    float t1 = p1.y + p2.y + s3[1];
    float t2 = p1.z + p2.z + s3[2];
    float t3 = p1.w + p2.w + s3[3];
    t0 = (t0 >= 0.f) ? t0 : 0.2f * t0;
    t1 = (t1 >= 0.f) ? t1 : 0.2f * t1;
    t2 = (t2 >= 0.f) ? t2 : 0.2f * t2;
    t3 = (t3 >= 0.f) ? t3 : 0.2f * t3;
    float score = 0.25f * (t0 + t1 + t2 + t3);
    g_cpack[p] = make_int4(e, __float_as_int(score), r | ((lr + 1) << 20), 0);
}

// ---------------------------------------------------------------------------
// Launch 4 (PROFILED): fused select + MAC, warp-per-node (R9 skeleton,
// single int4 cpack gather, R12 MAC body). Self-cleans g_deg.
// ---------------------------------------------------------------------------
__global__ void __launch_bounds__(256, 2)
k_node_agg(const float* __restrict__ edge_attr,
           const int* __restrict__ labels,
           const float* __restrict__ weW,
           const float* __restrict__ web,
           float* __restrict__ out,
           int n) {
    __shared__ float  s_sc[8][MAXD];
    __shared__ int    s_eid[8][MAXD];
    __shared__ float  s_ka[8][TOPK];
    __shared__ int    s_ke[8][TOPK];
    __shared__ int    s_kr[8][TOPK];
    __shared__ float  s_eav[8][TOPK][ED];   // 10 KB
    __shared__ float2 s_hv[8][TOPK][32];    // 20 KB

    int tid = threadIdx.x;
    int lane = tid & 31, wl = tid >> 5;

    // weights for output columns 2*lane, 2*lane+1
    float2 w2[ED];
    #pragma unroll
    for (int k = 0; k < ED; k++)
        w2[k] = reinterpret_cast<const float2*>(weW + k * H)[lane];
    float2 b2 = reinterpret_cast<const float2*>(web)[lane];

    int warpG = (blockIdx.x * blockDim.x + tid) >> 5;
    int nwarps = (gridDim.x * blockDim.x) >> 5;

    for (int node = warpG; node < n; node += nwarps) {
        int d = g_deg[node], st = g_start[node];
        float acc0 = 0.f, acc1 = 0.f, acc2 = 0.f, acc3 = 0.f, acc4 = 0.f, acc5 = 0.f;
        int kk = 0;
        if (d > 0 && d <= 32) {
            // -------- register select path: ONE int4 gather --------
            int lc = labels[node];
            bool valid = lane < d;
            int4 P = g_cpack[st + (valid ? lane : 0)];
            int e = P.x; float sc = __int_as_float(P.y); int rl = P.z;
            if (!valid) { e = 0x7FFFFFFF; sc = -1e30f; }
            float mx = sc;
            #pragma unroll
            for (int off = 16; off; off >>= 1)
                mx = fmaxf(mx, __shfl_xor_sync(0xffffffffu, mx, off));
            float ex = valid ? expf(sc - mx) : 0.f;
            float sum = ex;
            #pragma unroll
            for (int off = 16; off; off >>= 1)
                sum += __shfl_xor_sync(0xffffffffu, sum, off);
            float invden = 1.f / sum;
            int cnt = 0;
            if (d > TOPK) {
                for (int j = 0; j < d; j++) {
                    float scj = __shfl_sync(0xffffffffu, sc, j);
                    int   ej  = __shfl_sync(0xffffffffu, e,  j);
                    cnt += (scj > sc) || (scj == sc && ej < e);
                }
            }
            bool keep = valid && (cnt < TOPK);
            unsigned bal = __ballot_sync(0xffffffffu, keep);
            kk = __popc(bal);
            int pos = __popc(bal & ((1u << lane) - 1u));
            if (keep) {
                int lr = (rl >> 20) - 1;
                int g = (lr < 0 || lc < 0) ? 2 : ((lr == lc) ? 0 : 1);
                s_ka[wl][pos] = ex * invden;
                s_ke[wl][pos] = e;
                s_kr[wl][pos] = (rl & 0xFFFFF) | (g << 20);
            }
            __syncwarp();
        } else if (d > 32 && d <= MAXD) {
            // -------- shared select path (rare) --------
            int lc = labels[node];
            for (int i = lane; i < d; i += 32) {
                int4 P = g_cpack[st + i];
                s_eid[wl][i] = P.x;
                s_sc[wl][i]  = __int_as_float(P.y);
            }
            __syncwarp();
            float mx = -1e30f;
            for (int i = lane; i < d; i += 32) mx = fmaxf(mx, s_sc[wl][i]);
            #pragma unroll
            for (int off = 16; off; off >>= 1)
                mx = fmaxf(mx, __shfl_xor_sync(0xffffffffu, mx, off));
            float sum = 0.f;
            for (int i = lane; i < d; i += 32) sum += expf(s_sc[wl][i] - mx);
            #pragma unroll
            for (int off = 16; off; off >>= 1)
                sum += __shfl_xor_sync(0xffffffffu, sum, off);
            float invden = 1.f / sum;
            for (int base = 0; base < d; base += 32) {
                int i = base + lane;
                bool valid = (i < d);
                bool keep = false;
                float a = 0.f;
                if (valid) {
                    float sci = s_sc[wl][i];
                    int ei = s_eid[wl][i];
                    int c = 0;
                    for (int j = 0; j < d; j++) {
                        float scj = s_sc[wl][j];
                        c += (scj > sci) || (scj == sci && s_eid[wl][j] < ei);
                    }
                    keep = (c < TOPK);
                    if (keep) a = expf(sci - mx) * invden;
                }
                unsigned bal = __ballot_sync(0xffffffffu, valid && keep);
                int pos = kk + __popc(bal & ((1u << lane) - 1u));
                if (valid && keep) {
                    int rl = g_cpack[st + i].z;
                    int lr = (rl >> 20) - 1;
                    int g = (lr < 0 || lc < 0) ? 2 : ((lr == lc) ? 0 : 1);
                    s_ka[wl][pos] = a;
                    s_ke[wl][pos] = s_eid[wl][i];
                    s_kr[wl][pos] = (rl & 0xFFFFF) | (g << 20);
                }
                kk += __popc(bal);
            }
            __syncwarp();
        } else if (d > MAXD) {
            // -------- giant fallback (effectively never): direct accumulate --
            int lc = labels[node];
            float mx = -1e30f;
            for (int i = lane; i < d; i += 32)
                mx = fmaxf(mx, __int_as_float(g_cpack[st + i].y));
            #pragma unroll
            for (int off = 16; off; off >>= 1)
                mx = fmaxf(mx, __shfl_xor_sync(0xffffffffu, mx, off));
            float sum = 0.f;
            for (int i = lane; i < d; i += 32)
                sum += expf(__int_as_float(g_cpack[st + i].y) - mx);
            #pragma unroll
            for (int off = 16; off; off >>= 1)
                sum += __shfl_xor_sync(0xffffffffu, sum, off);
            float invden = 1.f / sum;
            for (int i = 0; i < d; i++) {
                int4 P = g_cpack[st + i];
                float sci = __int_as_float(P.y);
                int c = 0;
                for (int j = lane; j < d; j += 32) {
                    int4 Q = g_cpack[st + j];
                    float scj = __int_as_float(Q.y);
                    c += (scj > sci) || (scj == sci && Q.x < P.x);
                }
                #pragma unroll
                for (int off = 16; off; off >>= 1)
                    c += __shfl_xor_sync(0xffffffffu, c, off);
                if (c >= TOPK) continue;
                float a = expf(sci - mx) * invden;
                int rl = P.z;
                int r = rl & 0xFFFFF;
                int lr = (rl >> 20) - 1;
                int g = (lr < 0 || lc < 0) ? 2 : ((lr == lc) ? 0 : 1);
                float2 hv = reinterpret_cast<const float2*>(g_hW + (size_t)r * H)[lane];
                float eav = edge_attr[(size_t)P.x * ED + lane];
                float m0 = b2.x, m1 = b2.y;
                #pragma unroll
                for (int k = 0; k < ED; k++) {
                    float bv = __shfl_sync(0xffffffffu, eav, k);
                    m0 += bv * w2[k].x;
                    m1 += bv * w2[k].y;
                }
                m0 = fmaxf(m0 + hv.x, 0.f);
                m1 = fmaxf(m1 + hv.y, 0.f);
                if (g == 0)      { acc0 += a * m0; acc1 += a * m1; }
                else if (g == 1) { acc2 += a * m0; acc3 += a * m1; }
                else             { acc4 += a * m0; acc5 += a * m1; }
            }
        }

        if (kk > 0) {
            // per-lane regs for kept edges
            int e_reg = 0, r_reg = 0, g_reg = 2;
            float a_reg = 0.f;
            if (lane < kk) {
                e_reg = s_ke[wl][lane];
                a_reg = s_ka[wl][lane];
                int rl = s_kr[wl][lane];
                r_reg = rl & 0xFFFFF;
                g_reg = rl >> 20;
            }
            // batch prefetch (independent loads -> high MLP)
            for (int i = 0; i < kk; i++) {
                int e_i = __shfl_sync(0xffffffffu, e_reg, i);
                int r_i = __shfl_sync(0xffffffffu, r_reg, i);
                s_eav[wl][i][lane] = edge_attr[(size_t)e_i * ED + lane];
                s_hv[wl][i][lane]  = reinterpret_cast<const float2*>(g_hW + (size_t)r_i * H)[lane];
            }
            __syncwarp();
            // MAC: float4 broadcast LDS + FFMA (2 cols/lane)
            for (int i = 0; i < kk; i++) {
                float a = __shfl_sync(0xffffffffu, a_reg, i);
                int   g = __shfl_sync(0xffffffffu, g_reg, i);
                float m0 = b2.x, m1 = b2.y;
                const float4* ev = reinterpret_cast<const float4*>(s_eav[wl][i]);
                #pragma unroll
                for (int k4 = 0; k4 < 8; k4++) {
                    float4 v = ev[k4];
                    int k = k4 * 4;
                    m0 += v.x * w2[k].x;     m1 += v.x * w2[k].y;
                    m0 += v.y * w2[k + 1].x; m1 += v.y * w2[k + 1].y;
                    m0 += v.z * w2[k + 2].x; m1 += v.z * w2[k + 2].y;
                    m0 += v.w * w2[k + 3].x; m1 += v.w * w2[k + 3].y;
                }
                float2 hv = s_hv[wl][i][lane];
                m0 = fmaxf(m0 + hv.x, 0.f);
                m1 = fmaxf(m1 + hv.y, 0.f);
                if (g == 0)      { acc0 += a * m0; acc1 += a * m1; }
                else if (g == 1) { acc2 += a * m0; acc3 += a * m1; }
                else             { acc4 += a * m0; acc5 += a * m1; }
            }
            __syncwarp();
        }

        // self-clean for next graph replay
        g_deg[node] = 0;

        size_t ob = (size_t)node * (3 * H);
        reinterpret_cast<float2*>(out + ob)[lane]         = make_float2(acc0, acc1);
        reinterpret_cast<float2*>(out + ob + H)[lane]     = make_float2(acc2, acc3);
        reinterpret_cast<float2*>(out + ob + 2 * H)[lane] = make_float2(acc4, acc5);
    }
}

// ---------------------------------------------------------------------------
extern "C" void kernel_launch(void* const* d_in, const int* in_sizes, int n_in,
                              void* d_out, int out_size) {
    const float* h         = (const float*)d_in[0];
    const int*   edge_idx  = (const int*)  d_in[1];
    const float* edge_attr = (const float*)d_in[2];
    const int*   labels    = (const int*)  d_in[3];
    const float* attn_w    = (const float*)d_in[4];
    const float* whW       = (const float*)d_in[5];
    const float* whb       = (const float*)d_in[6];
    const float* weW       = (const float*)d_in[7];
    const float* web       = (const float*)d_in[8];
    float* out = (float*)d_out;

    int n = in_sizes[0] / H;
    int e = in_sizes[1] / 2;
    const int* row = edge_idx;
    const int* col = edge_idx + e;

    int nbG = (n + 63) / 64;
    int nbC = (e + 255) / 256;
    int nbS = (n + 2047) / 2048;   // <= 64

    k_gemm_count<<<nbG + nbC, 256>>>(h, whW, whb, attn_w, col, n, e, nbG);
    k_scan_onepass<<<nbS, 256>>>(n);
    k_score_scatter<<<(e + 255) / 256, 256>>>(row, col, edge_attr, attn_w, labels, e);
    k_node_agg<<<592, 256>>>(edge_attr, labels, weW, web, out, n);  // profiled slot
}